// round 1
// baseline (speedup 1.0000x reference)
#include <cuda_runtime.h>
#include <math.h>

// Problem dims
#define BB   256
#define LL   128
#define VOC  4096
#define EENC 1024
#define DDEC 1024
#define EEMB 512

// ---------------- scratch (no allocations allowed) ----------------
// Tw  : 32768 x 1024 weighted-tanh partials of the score GEMM
// G1  : 256 x 1024   (h @ W2^T + W2_b + W1_b), later reused as fc1 output t (256x512)
// RNN : 256 x 1536   [context | x_emb]
// GI  : 256 x 3072
// GH  : 256 x 3072
#define OFF_TW   0ull
#define OFF_G1   (OFF_TW  + 32768ull * 1024ull)
#define OFF_RNN  (OFF_G1  + 256ull * 1024ull)
#define OFF_GI   (OFF_RNN + 256ull * 1536ull)
#define OFF_GH   (OFF_GI  + 256ull * 3072ull)
#define SCRATCH_TOTAL (OFF_GH + 256ull * 3072ull)

__device__ float g_scratch[SCRATCH_TOTAL];

// ---------------- f32x2 packed math helpers ----------------
__device__ __forceinline__ unsigned long long pack2(float x, float y) {
    unsigned long long r;
    asm("mov.b64 %0, {%1,%2};" : "=l"(r) : "f"(x), "f"(y));
    return r;
}
__device__ __forceinline__ unsigned long long fma2(unsigned long long a,
                                                   unsigned long long b,
                                                   unsigned long long c) {
    unsigned long long d;
    asm("fma.rn.f32x2 %0, %1, %2, %3;" : "=l"(d) : "l"(a), "l"(b), "l"(c));
    return d;
}
__device__ __forceinline__ float2 unpack2(unsigned long long v) {
    float2 f;
    asm("mov.b64 {%0,%1}, %2;" : "=f"(f.x), "=f"(f.y) : "l"(v));
    return f;
}

// ---------------- generic tiled SGEMM: C = A(MxK) @ W(NxK)^T + epilogue -----
// Tile 128x128, K-step 16, 256 threads, 8x8 per thread in 4+4 split layout.
// Requirements (all satisfied by our shapes): M%128==0, N%128==0, K%16==0.
enum { EPI_BIAS = 0, EPI_BIAS2 = 1, EPI_TANH = 2, EPI_SCORE = 3 };

template <int EPI>
__global__ __launch_bounds__(256, 2)
void sgemm128(const float* __restrict__ A, int lda,
              const float* __restrict__ W,             // row-major N x K
              const float* __restrict__ b1,
              const float* __restrict__ b2,
              float* __restrict__ C, int ldc,
              int K,
              const float* __restrict__ g1,            // EPI_SCORE: [gridDim.y x 1024]
              const float* __restrict__ vw)            // EPI_SCORE: [1024]
{
    __shared__ float As[16][132];
    __shared__ float Ws[16][132];

    const int tid  = threadIdx.x;
    const int tx   = tid & 15;          // 0..15 -> column groups
    const int ty   = tid >> 4;          // 0..15 -> row groups
    const int brow = blockIdx.y * 128;
    const int bcol = blockIdx.x * 128;

    // loader mapping: 256 threads * 2 float4 = 128 rows x 16 k
    const int lr = tid >> 2;            // 0..63
    const int lk = (tid & 3) << 2;      // 0,4,8,12

    const float* Ap = A + (size_t)(brow + lr) * lda + lk;
    const float* Wp = W + (size_t)(bcol + lr) * K + lk;

    unsigned long long acc[8][4];
#pragma unroll
    for (int i = 0; i < 8; i++)
#pragma unroll
        for (int j = 0; j < 4; j++) acc[i][j] = 0ull;

    for (int k0 = 0; k0 < K; k0 += 16) {
        float4 a0 = *(const float4*)Ap;
        float4 a1 = *(const float4*)(Ap + (size_t)64 * lda);
        float4 w0 = *(const float4*)Wp;
        float4 w1 = *(const float4*)(Wp + (size_t)64 * K);

        __syncthreads();   // previous compute done before overwriting smem
        As[lk + 0][lr] = a0.x; As[lk + 1][lr] = a0.y;
        As[lk + 2][lr] = a0.z; As[lk + 3][lr] = a0.w;
        As[lk + 0][lr + 64] = a1.x; As[lk + 1][lr + 64] = a1.y;
        As[lk + 2][lr + 64] = a1.z; As[lk + 3][lr + 64] = a1.w;
        Ws[lk + 0][lr] = w0.x; Ws[lk + 1][lr] = w0.y;
        Ws[lk + 2][lr] = w0.z; Ws[lk + 3][lr] = w0.w;
        Ws[lk + 0][lr + 64] = w1.x; Ws[lk + 1][lr + 64] = w1.y;
        Ws[lk + 2][lr + 64] = w1.z; Ws[lk + 3][lr + 64] = w1.w;
        __syncthreads();

#pragma unroll
        for (int kk = 0; kk < 16; kk++) {
            float4 av0 = *(const float4*)&As[kk][ty * 4];
            float4 av1 = *(const float4*)&As[kk][64 + ty * 4];
            float4 bv0 = *(const float4*)&Ws[kk][tx * 4];
            float4 bv1 = *(const float4*)&Ws[kk][64 + tx * 4];
            unsigned long long bp0 = pack2(bv0.x, bv0.y);
            unsigned long long bp1 = pack2(bv0.z, bv0.w);
            unsigned long long bp2 = pack2(bv1.x, bv1.y);
            unsigned long long bp3 = pack2(bv1.z, bv1.w);
            float a[8] = {av0.x, av0.y, av0.z, av0.w, av1.x, av1.y, av1.z, av1.w};
#pragma unroll
            for (int i = 0; i < 8; i++) {
                unsigned long long ad = pack2(a[i], a[i]);
                acc[i][0] = fma2(ad, bp0, acc[i][0]);
                acc[i][1] = fma2(ad, bp1, acc[i][1]);
                acc[i][2] = fma2(ad, bp2, acc[i][2]);
                acc[i][3] = fma2(ad, bp3, acc[i][3]);
            }
        }
        Ap += 16;
        Wp += 16;
    }

    // ---- epilogue ----
#pragma unroll
    for (int i = 0; i < 8; i++) {
        const int r = brow + ((i < 4) ? (ty * 4 + i) : (64 + ty * 4 + (i - 4)));
#pragma unroll
        for (int h = 0; h < 2; h++) {
            const int c = bcol + tx * 4 + h * 64;
            float2 p0 = unpack2(acc[i][h * 2 + 0]);
            float2 p1 = unpack2(acc[i][h * 2 + 1]);
            float v0 = p0.x, v1 = p0.y, v2 = p1.x, v3 = p1.y;

            if (EPI == EPI_BIAS || EPI == EPI_BIAS2 || EPI == EPI_TANH) {
                float4 bb = *(const float4*)(b1 + c);
                v0 += bb.x; v1 += bb.y; v2 += bb.z; v3 += bb.w;
                if (EPI == EPI_BIAS2) {
                    float4 b2v = *(const float4*)(b2 + c);
                    v0 += b2v.x; v1 += b2v.y; v2 += b2v.z; v3 += b2v.w;
                }
                if (EPI == EPI_TANH) {
                    v0 = tanhf(v0); v1 = tanhf(v1); v2 = tanhf(v2); v3 = tanhf(v3);
                }
            } else {  // EPI_SCORE: tanh(acc + g1[b,c]) * vw[c]
                const float* g = g1 + (size_t)blockIdx.y * 1024 + c;
                float4 gg = *(const float4*)g;
                float4 ww = *(const float4*)(vw + c);
                v0 = tanhf(v0 + gg.x) * ww.x;
                v1 = tanhf(v1 + gg.y) * ww.y;
                v2 = tanhf(v2 + gg.z) * ww.z;
                v3 = tanhf(v3 + gg.w) * ww.w;
            }
            float4 outv = make_float4(v0, v1, v2, v3);
            *(float4*)(C + (size_t)r * ldc + c) = outv;
        }
    }
}

// ---------------- softmax + context (one block per batch element) ----------
__global__ __launch_bounds__(256)
void attn_softmax_context(const float* __restrict__ Tw,
                          const float* __restrict__ enc,
                          const float* __restrict__ Vb,
                          float* __restrict__ attn_out,  // [B*L]
                          float* __restrict__ rnn)       // [B x 1536], ctx -> cols 0..1023
{
    const int b    = blockIdx.x;
    const int tid  = threadIdx.x;
    const int warp = tid >> 5;
    const int lane = tid & 31;

    __shared__ float logit[LL];

    // 1) logits: row sums of weighted-tanh partials (+ V_b)
    for (int l = warp; l < LL; l += 8) {
        const float* row = Tw + (size_t)(b * LL + l) * 1024;
        float s = 0.f;
        for (int d = lane; d < 1024; d += 32) s += row[d];
#pragma unroll
        for (int o = 16; o; o >>= 1) s += __shfl_xor_sync(0xffffffffu, s, o);
        if (lane == 0) logit[l] = s + Vb[0];
    }
    __syncthreads();

    // 2) softmax over L (single warp)
    if (tid < 32) {
        float m = -1e30f;
        for (int l = lane; l < LL; l += 32) m = fmaxf(m, logit[l]);
#pragma unroll
        for (int o = 16; o; o >>= 1) m = fmaxf(m, __shfl_xor_sync(0xffffffffu, m, o));
        float s = 0.f;
        for (int l = lane; l < LL; l += 32) {
            float e = expf(logit[l] - m);
            logit[l] = e;
            s += e;
        }
#pragma unroll
        for (int o = 16; o; o >>= 1) s += __shfl_xor_sync(0xffffffffu, s, o);
        float inv = 1.f / s;
        for (int l = lane; l < LL; l += 32) logit[l] *= inv;
    }
    __syncthreads();

    if (tid < LL) attn_out[b * LL + tid] = logit[tid];

    // 3) context[b, e] = sum_l attn[l] * enc[b,l,e]  (4 cols per thread, coalesced)
    float4 acc = make_float4(0.f, 0.f, 0.f, 0.f);
    const float* encb = enc + (size_t)b * LL * EENC;
    const int e4 = tid * 4;
#pragma unroll 4
    for (int l = 0; l < LL; l++) {
        float a = logit[l];
        float4 v = *(const float4*)(encb + (size_t)l * EENC + e4);
        acc.x += a * v.x; acc.y += a * v.y; acc.z += a * v.z; acc.w += a * v.w;
    }
    *(float4*)(rnn + (size_t)b * 1536 + e4) = acc;
}

// ---------------- GRU gates ----------------
__global__ __launch_bounds__(256)
void gru_gate(const float* __restrict__ gi, const float* __restrict__ gh,
              const float* __restrict__ h0, float* __restrict__ hnew)
{
    const int idx = blockIdx.x * blockDim.x + threadIdx.x;  // B*DDEC
    const int b = idx >> 10;
    const int d = idx & 1023;
    const float* gib = gi + (size_t)b * 3072;
    const float* ghb = gh + (size_t)b * 3072;
    float r = 1.f / (1.f + expf(-(gib[d] + ghb[d])));
    float z = 1.f / (1.f + expf(-(gib[1024 + d] + ghb[1024 + d])));
    float n = tanhf(gib[2048 + d] + r * ghb[2048 + d]);
    hnew[idx] = (1.f - z) * n + z * h0[idx];
}

// ---------------- launch ----------------
extern "C" void kernel_launch(void* const* d_in, const int* in_sizes, int n_in,
                              void* d_out, int out_size)
{
    (void)in_sizes; (void)n_in; (void)out_size;

    const float* x      = (const float*)d_in[0];   // (256, 4096)
    const float* hidden = (const float*)d_in[1];   // (256, 1024)
    const float* enc    = (const float*)d_in[2];   // (256, 128, 1024)
    const float* W1_w   = (const float*)d_in[3];
    const float* W1_b   = (const float*)d_in[4];
    const float* W2_w   = (const float*)d_in[5];
    const float* W2_b   = (const float*)d_in[6];
    const float* V_w    = (const float*)d_in[7];
    const float* V_b    = (const float*)d_in[8];
    const float* o2e_w  = (const float*)d_in[9];
    const float* o2e_b  = (const float*)d_in[10];
    const float* gwi    = (const float*)d_in[11];
    const float* gwh    = (const float*)d_in[12];
    const float* gbi    = (const float*)d_in[13];
    const float* gbh    = (const float*)d_in[14];
    const float* f1w    = (const float*)d_in[15];
    const float* f1b    = (const float*)d_in[16];
    const float* f2w    = (const float*)d_in[17];
    const float* f2b    = (const float*)d_in[18];

    float* out  = (float*)d_out;                 // (256, 4096)
    float* hnew = out + (size_t)BB * VOC;        // (256, 1024)
    float* attn = hnew + (size_t)BB * DDEC;      // (256, 128)

    float* scratch = nullptr;
    cudaGetSymbolAddress((void**)&scratch, g_scratch);
    float* Tw  = scratch + OFF_TW;
    float* g1  = scratch + OFF_G1;
    float* rnn = scratch + OFF_RNN;
    float* gi  = scratch + OFF_GI;
    float* gh  = scratch + OFF_GH;

    dim3 blk(256);

    // 1) g1 = h0 @ W2^T + W2_b + W1_b                         (256 x 1024, K=1024)
    sgemm128<EPI_BIAS2><<<dim3(1024 / 128, 256 / 128), blk>>>(
        hidden, 1024, W2_w, W2_b, W1_b, g1, 1024, 1024, nullptr, nullptr);

    // 2) Tw = tanh(enc @ W1^T + g1[b]) * V_w                  (32768 x 1024, K=1024)
    sgemm128<EPI_SCORE><<<dim3(1024 / 128, 32768 / 128), blk>>>(
        enc, 1024, W1_w, nullptr, nullptr, Tw, 1024, 1024, g1, V_w);

    // 3) softmax over L + attn out + context -> rnn[:, 0:1024]
    attn_softmax_context<<<BB, 256>>>(Tw, enc, V_b, attn, rnn);

    // 4) x_emb = x @ out2emb^T + b -> rnn[:, 1024:1536]       (256 x 512, K=4096)
    sgemm128<EPI_BIAS><<<dim3(512 / 128, 256 / 128), blk>>>(
        x, 4096, o2e_w, o2e_b, nullptr, rnn + 1024, 1536, 4096, nullptr, nullptr);

    // 5) gi = rnn_in @ gru_wi^T + gru_bi                      (256 x 3072, K=1536)
    sgemm128<EPI_BIAS><<<dim3(3072 / 128, 256 / 128), blk>>>(
        rnn, 1536, gwi, gbi, nullptr, gi, 3072, 1536, nullptr, nullptr);

    // 6) gh = h0 @ gru_wh^T + gru_bh                          (256 x 3072, K=1024)
    sgemm128<EPI_BIAS><<<dim3(3072 / 128, 256 / 128), blk>>>(
        hidden, 1024, gwh, gbh, nullptr, gh, 3072, 1024, nullptr, nullptr);

    // 7) GRU gates -> h_new (also an output)
    gru_gate<<<(BB * DDEC) / 256, 256>>>(gi, gh, hidden, hnew);

    // 8) t = tanh(h_new @ fc1^T + fc1_b) -> reuse g1          (256 x 512, K=1024)
    sgemm128<EPI_TANH><<<dim3(512 / 128, 256 / 128), blk>>>(
        hnew, 1024, f1w, f1b, nullptr, g1, 512, 1024, nullptr, nullptr);

    // 9) out = t @ fc2^T + fc2_b                              (256 x 4096, K=512)
    sgemm128<EPI_BIAS><<<dim3(4096 / 128, 256 / 128), blk>>>(
        g1, 512, f2w, f2b, nullptr, out, 4096, 512, nullptr, nullptr);
}

// round 3
// speedup vs baseline: 1.8168x; 1.8168x over previous
#include <cuda_runtime.h>
#include <cuda_bf16.h>
#include <cstdint>
#include <math.h>

// Problem dims
#define BB   256
#define LL   128
#define VOC  4096
#define EENC 1024
#define DDEC 1024
#define EEMB 512

// ======================= scratch (module-load allocated) ==================
// bf16 hi/lo pools (element offsets)
#define OFF_ENC   0ull
#define OFF_W1    (OFF_ENC + 33554432ull)
#define OFF_W2    (OFF_W1  + 1048576ull)
#define OFF_O2E   (OFF_W2  + 1048576ull)
#define OFF_GWI   (OFF_O2E + 2097152ull)
#define OFF_GWH   (OFF_GWI + 4718592ull)
#define OFF_F1    (OFF_GWH + 3145728ull)
#define OFF_F2    (OFF_F1  + 524288ull)
#define OFF_X     (OFF_F2  + 2097152ull)
#define OFF_HID   (OFF_X   + 1048576ull)
#define OFF_RNN   (OFF_HID + 262144ull)
#define OFF_HNEW  (OFF_RNN + 393216ull)
#define OFF_T     (OFF_HNEW+ 262144ull)
#define BF_TOTAL  (OFF_T   + 131072ull)

__device__ __nv_bfloat16 g_bh[BF_TOTAL];
__device__ __nv_bfloat16 g_bl[BF_TOTAL];

// fp32 pool
#define F_G1    0ull
#define F_RNN   (F_G1   + 262144ull)
#define F_GI    (F_RNN  + 393216ull)
#define F_GH    (F_GI   + 786432ull)
#define F_T     (F_GH   + 786432ull)
#define F_PART  (F_T    + 131072ull)
#define F_TOTAL (F_PART + 262144ull)

__device__ float g_f32[F_TOTAL];

// ======================= small helpers ====================================
__device__ __forceinline__ void cp16(uint32_t s, const void* g) {
    asm volatile("cp.async.cg.shared.global [%0], [%1], 16;"
                 :: "r"(s), "l"(__cvta_generic_to_global(g)));
}
__device__ __forceinline__ void ldm4(uint32_t* r, uint32_t addr) {
    asm volatile("ldmatrix.sync.aligned.m8n8.x4.shared.b16 {%0,%1,%2,%3}, [%4];"
        : "=r"(r[0]), "=r"(r[1]), "=r"(r[2]), "=r"(r[3]) : "r"(addr));
}
__device__ __forceinline__ void mma16816(float* c, const uint32_t* a, const uint32_t* b) {
    asm volatile("mma.sync.aligned.m16n8k16.row.col.f32.bf16.bf16.f32 "
        "{%0,%1,%2,%3}, {%4,%5,%6,%7}, {%8,%9}, {%0,%1,%2,%3};"
        : "+f"(c[0]), "+f"(c[1]), "+f"(c[2]), "+f"(c[3])
        : "r"(a[0]), "r"(a[1]), "r"(a[2]), "r"(a[3]), "r"(b[0]), "r"(b[1]));
}

// ======================= fp32 -> bf16 hi/lo split =========================
__global__ __launch_bounds__(256)
void f32_split(const float* __restrict__ in, __nv_bfloat16* __restrict__ hi,
               __nv_bfloat16* __restrict__ lo, int n2)
{
    int i = blockIdx.x * blockDim.x + threadIdx.x;
    if (i >= n2) return;
    float2 v = ((const float2*)in)[i];
    __nv_bfloat16 h0 = __float2bfloat16(v.x);
    __nv_bfloat16 h1 = __float2bfloat16(v.y);
    float r0 = v.x - __bfloat162float(h0);
    float r1 = v.y - __bfloat162float(h1);
    __nv_bfloat162 hp; hp.x = h0; hp.y = h1;
    __nv_bfloat162 lp; lp.x = __float2bfloat16(r0); lp.y = __float2bfloat16(r1);
    ((__nv_bfloat162*)hi)[i] = hp;
    ((__nv_bfloat162*)lo)[i] = lp;
}

// ======================= mma.sync GEMM: C = A @ W^T =======================
// A: M x K (bf16 hi/lo), W: N x K (bf16 hi/lo), K-major row-major.
// Block tile 128x128, BK=32, 8 warps (2 m-groups x 4 n-groups), warp tile 64x32.
// Compensated bf16x3: D += Ah*Wh + Al*Wh + Ah*Wl   (fp32 accumulate)
enum { EPI_BIAS = 0, EPI_BIAS2 = 1, EPI_TANH = 2, EPI_SCORE = 3 };

#define ROWB    80                       // smem row stride bytes (conflict-free ldmatrix)
#define TILE_SB (128 * ROWB)             // 10240 B per tile
#define STAGE_SB (4 * TILE_SB)           // Ah Al Wh Wl = 40960 B
#define SM_PART (2 * STAGE_SB)           // 81920: 128 floats for score partials
#define GEMM_SMEM (SM_PART + 512 + 32)

template <int EPI>
__global__ __launch_bounds__(256, 1)
void tc_gemm(const __nv_bfloat16* __restrict__ Ah, const __nv_bfloat16* __restrict__ Al,
             const __nv_bfloat16* __restrict__ Wh, const __nv_bfloat16* __restrict__ Wl,
             int K, float* __restrict__ C, int ldc,
             const float* __restrict__ b1, const float* __restrict__ b2,
             const float* __restrict__ g1, const float* __restrict__ vw,
             float* __restrict__ partial)
{
    extern __shared__ __align__(128) char smem[];
    const uint32_t sbase = (uint32_t)__cvta_generic_to_shared(smem);
    float* part_sm = (float*)(smem + SM_PART);

    const int tid  = threadIdx.x;
    const int wid  = tid >> 5;
    const int lane = tid & 31;
    const int brow = blockIdx.y * 128;
    const int bcol = blockIdx.x * 128;
    const int wm   = wid >> 2;           // 0..1  -> m offset 64*wm
    const int wn   = wid & 3;            // 0..3  -> n offset 32*wn
    const int m64  = wm * 64;
    const int n32  = wn * 32;

    if (EPI == EPI_SCORE) {
        if (tid < 128) part_sm[tid] = 0.f;
    }

    // ---- loader mapping: 256 threads, each 2 x cp16 per tile ----
    const int lrow = tid >> 1;           // 0..127
    const int lc0  = (tid & 1) * 2;      // 0 or 2 (16B chunk index)
    const size_t aoff = (size_t)(brow + lrow) * K;
    const size_t woff = (size_t)(bcol + lrow) * K;

    auto load_stage = [&](int stage, int k0) {
        const uint32_t sb = sbase + stage * STAGE_SB + lrow * ROWB;
        const char* pAh = (const char*)(Ah + aoff + k0);
        const char* pAl = (const char*)(Al + aoff + k0);
        const char* pWh = (const char*)(Wh + woff + k0);
        const char* pWl = (const char*)(Wl + woff + k0);
        #pragma unroll
        for (int c = lc0; c < lc0 + 2; c++) {
            cp16(sb + 0 * TILE_SB + c * 16, pAh + c * 16);
            cp16(sb + 1 * TILE_SB + c * 16, pAl + c * 16);
            cp16(sb + 2 * TILE_SB + c * 16, pWh + c * 16);
            cp16(sb + 3 * TILE_SB + c * 16, pWl + c * 16);
        }
    };

    const int nk = K >> 5;               // K / 32

    load_stage(0, 0);
    asm volatile("cp.async.commit_group;");
    if (nk > 1) load_stage(1, 32);
    asm volatile("cp.async.commit_group;");

    float acc[4][4][4];
    #pragma unroll
    for (int i = 0; i < 4; i++)
        #pragma unroll
        for (int j = 0; j < 4; j++)
            #pragma unroll
            for (int q = 0; q < 4; q++) acc[i][j][q] = 0.f;

    // fragment address components (within-tile)
    const int arow_l = m64 + (lane & 7) + ((lane >> 3) & 1) * 8;
    const uint32_t akb = ((lane >> 4) & 1) * 16;
    const int nrow_l = n32 + (lane & 7) + ((lane >> 4) & 1) * 8;
    const uint32_t bkb = ((lane >> 3) & 1) * 16;

    for (int c = 0; c < nk; c++) {
        asm volatile("cp.async.wait_group %0;" :: "n"(1));
        __syncthreads();

        const uint32_t sb = sbase + (c & 1) * STAGE_SB;
        #pragma unroll
        for (int kk = 0; kk < 2; kk++) {     // two k16 halves of BK=32
            const uint32_t kbyte = kk * 32;
            uint32_t afh[4][4], afl[4][4], bfh[4][2], bfl[4][2];
            #pragma unroll
            for (int mt = 0; mt < 4; mt++) {
                uint32_t ra = (uint32_t)((arow_l + mt * 16) * ROWB) + akb + kbyte;
                ldm4(afh[mt], sb + 0 * TILE_SB + ra);
                ldm4(afl[mt], sb + 1 * TILE_SB + ra);
            }
            #pragma unroll
            for (int np = 0; np < 2; np++) {
                uint32_t rb = (uint32_t)((nrow_l + np * 16) * ROWB) + bkb + kbyte;
                uint32_t th[4], tl[4];
                ldm4(th, sb + 2 * TILE_SB + rb);
                ldm4(tl, sb + 3 * TILE_SB + rb);
                bfh[2 * np][0] = th[0]; bfh[2 * np][1] = th[1];
                bfh[2 * np + 1][0] = th[2]; bfh[2 * np + 1][1] = th[3];
                bfl[2 * np][0] = tl[0]; bfl[2 * np][1] = tl[1];
                bfl[2 * np + 1][0] = tl[2]; bfl[2 * np + 1][1] = tl[3];
            }
            #pragma unroll
            for (int mt = 0; mt < 4; mt++)
                #pragma unroll
                for (int nt = 0; nt < 4; nt++) {
                    mma16816(acc[mt][nt], afh[mt], bfh[nt]);
                    mma16816(acc[mt][nt], afl[mt], bfh[nt]);
                    mma16816(acc[mt][nt], afh[mt], bfl[nt]);
                }
        }
        __syncthreads();

        if (c + 2 < nk) load_stage(c & 1, (c + 2) * 32);
        asm volatile("cp.async.commit_group;");
    }

    // ---- epilogue ----
    const int rloc0 = m64 + (lane >> 2);          // +mt*16, and +8 for upper half
    const int cloc0 = n32 + (lane & 3) * 2;       // +nt*8

    if (EPI == EPI_SCORE) {
        const float* g1r = g1 + (size_t)blockIdx.y * 1024;
        #pragma unroll
        for (int mt = 0; mt < 4; mt++) {
            float s0 = 0.f, s1 = 0.f;
            #pragma unroll
            for (int nt = 0; nt < 4; nt++) {
                int col = bcol + cloc0 + nt * 8;
                float gw0 = g1r[col],     vw0 = vw[col];
                float gw1 = g1r[col + 1], vw1 = vw[col + 1];
                s0 += tanhf(acc[mt][nt][0] + gw0) * vw0;
                s0 += tanhf(acc[mt][nt][1] + gw1) * vw1;
                s1 += tanhf(acc[mt][nt][2] + gw0) * vw0;
                s1 += tanhf(acc[mt][nt][3] + gw1) * vw1;
            }
            atomicAdd(&part_sm[rloc0 + mt * 16], s0);
            atomicAdd(&part_sm[rloc0 + mt * 16 + 8], s1);
        }
        __syncthreads();
        if (tid < 128)
            partial[(size_t)(brow + tid) * gridDim.x + blockIdx.x] = part_sm[tid];
    } else {
        #pragma unroll
        for (int mt = 0; mt < 4; mt++) {
            const int r0 = brow + rloc0 + mt * 16;
            #pragma unroll
            for (int nt = 0; nt < 4; nt++) {
                const int col = bcol + cloc0 + nt * 8;
                float2 bb = *(const float2*)(b1 + col);
                float v0 = acc[mt][nt][0] + bb.x;
                float v1 = acc[mt][nt][1] + bb.y;
                float v2 = acc[mt][nt][2] + bb.x;
                float v3 = acc[mt][nt][3] + bb.y;
                if (EPI == EPI_BIAS2) {
                    float2 cc = *(const float2*)(b2 + col);
                    v0 += cc.x; v1 += cc.y; v2 += cc.x; v3 += cc.y;
                }
                if (EPI == EPI_TANH) {
                    v0 = tanhf(v0); v1 = tanhf(v1); v2 = tanhf(v2); v3 = tanhf(v3);
                }
                *(float2*)(C + (size_t)r0 * ldc + col)       = make_float2(v0, v1);
                *(float2*)(C + (size_t)(r0 + 8) * ldc + col) = make_float2(v2, v3);
            }
        }
    }
}

// ============== softmax + context (one block per batch element) ===========
__global__ __launch_bounds__(256)
void attn_softmax_context(const float* __restrict__ part, int npart,
                          const float* __restrict__ enc,
                          const float* __restrict__ Vb,
                          float* __restrict__ attn_out,  // [B*L]
                          float* __restrict__ rnn)       // [B x 1536], ctx cols 0..1023
{
    const int b   = blockIdx.x;
    const int tid = threadIdx.x;
    __shared__ float logit[LL];

    if (tid < LL) {
        const float* pr = part + (size_t)(b * LL + tid) * npart;
        float s = Vb[0];
        for (int j = 0; j < npart; j++) s += pr[j];
        logit[tid] = s;
    }
    __syncthreads();

    if (tid < 32) {
        const int lane = tid;
        float m = -1e30f;
        for (int l = lane; l < LL; l += 32) m = fmaxf(m, logit[l]);
        #pragma unroll
        for (int o = 16; o; o >>= 1) m = fmaxf(m, __shfl_xor_sync(0xffffffffu, m, o));
        float s = 0.f;
        for (int l = lane; l < LL; l += 32) {
            float e = expf(logit[l] - m);
            logit[l] = e;
            s += e;
        }
        #pragma unroll
        for (int o = 16; o; o >>= 1) s += __shfl_xor_sync(0xffffffffu, s, o);
        float inv = 1.f / s;
        for (int l = lane; l < LL; l += 32) logit[l] *= inv;
    }
    __syncthreads();

    if (tid < LL) attn_out[b * LL + tid] = logit[tid];

    float4 acc = make_float4(0.f, 0.f, 0.f, 0.f);
    const float* encb = enc + (size_t)b * LL * EENC;
    const int e4 = tid * 4;
    #pragma unroll 4
    for (int l = 0; l < LL; l++) {
        float a = logit[l];
        float4 v = *(const float4*)(encb + (size_t)l * EENC + e4);
        acc.x += a * v.x; acc.y += a * v.y; acc.z += a * v.z; acc.w += a * v.w;
    }
    *(float4*)(rnn + (size_t)b * 1536 + e4) = acc;
}

// ============================ GRU gates ===================================
__global__ __launch_bounds__(256)
void gru_gate(const float* __restrict__ gi, const float* __restrict__ gh,
              const float* __restrict__ h0, float* __restrict__ hnew)
{
    const int idx = blockIdx.x * blockDim.x + threadIdx.x;  // B*DDEC
    const int b = idx >> 10;
    const int d = idx & 1023;
    const float* gib = gi + (size_t)b * 3072;
    const float* ghb = gh + (size_t)b * 3072;
    float r = 1.f / (1.f + expf(-(gib[d] + ghb[d])));
    float z = 1.f / (1.f + expf(-(gib[1024 + d] + ghb[1024 + d])));
    float n = tanhf(gib[2048 + d] + r * ghb[2048 + d]);
    hnew[idx] = (1.f - z) * n + z * h0[idx];
}

// ============================ launch ======================================
extern "C" void kernel_launch(void* const* d_in, const int* in_sizes, int n_in,
                              void* d_out, int out_size)
{
    (void)in_sizes; (void)n_in; (void)out_size;

    const float* x      = (const float*)d_in[0];   // (256, 4096)
    const float* hidden = (const float*)d_in[1];   // (256, 1024)
    const float* enc    = (const float*)d_in[2];   // (256, 128, 1024)
    const float* W1_w   = (const float*)d_in[3];
    const float* W1_b   = (const float*)d_in[4];
    const float* W2_w   = (const float*)d_in[5];
    const float* W2_b   = (const float*)d_in[6];
    const float* V_w    = (const float*)d_in[7];
    const float* V_b    = (const float*)d_in[8];
    const float* o2e_w  = (const float*)d_in[9];
    const float* o2e_b  = (const float*)d_in[10];
    const float* gwi    = (const float*)d_in[11];
    const float* gwh    = (const float*)d_in[12];
    const float* gbi    = (const float*)d_in[13];
    const float* gbh    = (const float*)d_in[14];
    const float* f1w    = (const float*)d_in[15];
    const float* f1b    = (const float*)d_in[16];
    const float* f2w    = (const float*)d_in[17];
    const float* f2b    = (const float*)d_in[18];

    float* out  = (float*)d_out;                 // (256, 4096)
    float* hnew = out + (size_t)BB * VOC;        // (256, 1024)
    float* attn = hnew + (size_t)BB * DDEC;      // (256, 128)

    __nv_bfloat16* bh = nullptr;
    __nv_bfloat16* bl = nullptr;
    float* fs = nullptr;
    cudaGetSymbolAddress((void**)&bh, g_bh);
    cudaGetSymbolAddress((void**)&bl, g_bl);
    cudaGetSymbolAddress((void**)&fs, g_f32);

    float* g1   = fs + F_G1;
    float* rnn  = fs + F_RNN;
    float* gi   = fs + F_GI;
    float* gh   = fs + F_GH;
    float* tbuf = fs + F_T;
    float* part = fs + F_PART;

    cudaFuncSetAttribute(tc_gemm<EPI_BIAS>,  cudaFuncAttributeMaxDynamicSharedMemorySize, GEMM_SMEM);
    cudaFuncSetAttribute(tc_gemm<EPI_BIAS2>, cudaFuncAttributeMaxDynamicSharedMemorySize, GEMM_SMEM);
    cudaFuncSetAttribute(tc_gemm<EPI_TANH>,  cudaFuncAttributeMaxDynamicSharedMemorySize, GEMM_SMEM);
    cudaFuncSetAttribute(tc_gemm<EPI_SCORE>, cudaFuncAttributeMaxDynamicSharedMemorySize, GEMM_SMEM);

    // ---- conversions: inputs + weights -> bf16 hi/lo ----
    auto split = [&](const float* src, unsigned long long off, int nelem) {
        int n2 = nelem / 2;
        f32_split<<<(n2 + 255) / 256, 256>>>(src, bh + off, bl + off, n2);
    };
    split(enc,    OFF_ENC, 33554432);
    split(hidden, OFF_HID, 262144);
    split(x,      OFF_X,   1048576);
    split(W1_w,   OFF_W1,  1048576);
    split(W2_w,   OFF_W2,  1048576);
    split(o2e_w,  OFF_O2E, 2097152);
    split(gwi,    OFF_GWI, 4718592);
    split(gwh,    OFF_GWH, 3145728);
    split(f1w,    OFF_F1,  524288);
    split(f2w,    OFF_F2,  2097152);

    dim3 blk(256);

    // 1) g1 = h0 @ W2^T + W2_b + W1_b                 (256 x 1024, K=1024)
    tc_gemm<EPI_BIAS2><<<dim3(8, 2), blk, GEMM_SMEM>>>(
        bh + OFF_HID, bl + OFF_HID, bh + OFF_W2, bl + OFF_W2,
        1024, g1, 1024, W2_b, W1_b, nullptr, nullptr, nullptr);

    // 2) partial logits from big score GEMM           (32768 x 1024, K=1024)
    tc_gemm<EPI_SCORE><<<dim3(8, 256), blk, GEMM_SMEM>>>(
        bh + OFF_ENC, bl + OFF_ENC, bh + OFF_W1, bl + OFF_W1,
        1024, nullptr, 0, nullptr, nullptr, g1, V_w, part);

    // 3) softmax + attn out + context -> rnn[:, 0:1024]
    attn_softmax_context<<<BB, 256>>>(part, 8, enc, V_b, attn, rnn);

    // 4) x_emb = x @ out2emb^T + b -> rnn[:, 1024:1536] (256 x 512, K=4096)
    tc_gemm<EPI_BIAS><<<dim3(4, 2), blk, GEMM_SMEM>>>(
        bh + OFF_X, bl + OFF_X, bh + OFF_O2E, bl + OFF_O2E,
        4096, rnn + 1024, 1536, o2e_b, nullptr, nullptr, nullptr, nullptr);

    // 5) rnn -> bf16
    split(rnn, OFF_RNN, 393216);

    // 6) gi = rnn_in @ gru_wi^T + gru_bi              (256 x 3072, K=1536)
    tc_gemm<EPI_BIAS><<<dim3(24, 2), blk, GEMM_SMEM>>>(
        bh + OFF_RNN, bl + OFF_RNN, bh + OFF_GWI, bl + OFF_GWI,
        1536, gi, 3072, gbi, nullptr, nullptr, nullptr, nullptr);

    // 7) gh = h0 @ gru_wh^T + gru_bh                  (256 x 3072, K=1024)
    tc_gemm<EPI_BIAS><<<dim3(24, 2), blk, GEMM_SMEM>>>(
        bh + OFF_HID, bl + OFF_HID, bh + OFF_GWH, bl + OFF_GWH,
        1024, gh, 3072, gbh, nullptr, nullptr, nullptr, nullptr);

    // 8) GRU gates -> h_new (output)
    gru_gate<<<(BB * DDEC) / 256, 256>>>(gi, gh, hidden, hnew);

    // 9) h_new -> bf16
    split(hnew, OFF_HNEW, 262144);

    // 10) t = tanh(h_new @ fc1^T + fc1_b)             (256 x 512, K=1024)
    tc_gemm<EPI_TANH><<<dim3(4, 2), blk, GEMM_SMEM>>>(
        bh + OFF_HNEW, bl + OFF_HNEW, bh + OFF_F1, bl + OFF_F1,
        1024, tbuf, 512, f1b, nullptr, nullptr, nullptr, nullptr);

    // 11) t -> bf16
    split(tbuf, OFF_T, 131072);

    // 12) out = t @ fc2^T + fc2_b                     (256 x 4096, K=512)
    tc_gemm<EPI_BIAS><<<dim3(32, 2), blk, GEMM_SMEM>>>(
        bh + OFF_T, bl + OFF_T, bh + OFF_F2, bl + OFF_F2,
        512, out, 4096, f2b, nullptr, nullptr, nullptr, nullptr);
}